// round 1
// baseline (speedup 1.0000x reference)
#include <cuda_runtime.h>

// Problem dims
#define T_DIM 32
#define B_DIM 64
#define D_DIM 256
#define P_DIM 1024
#define M_TOT (T_DIM * B_DIM)   // 2048
#define KNOTS 17

// GEMM tiling
#define BM 128
#define BN 64
#define BK 16

// Scratch (static device globals — no runtime allocation)
__device__ float g_x[M_TOT * P_DIM];     // 8 MB: projections x[t*B+b][p]
__device__ float g_partial[512];         // block partials from trig kernel

// ---------------------------------------------------------------------------
// Kernel 1: x = proj @ normalize_cols(A). Column norms are computed inline:
// each thread sees all K=256 rows of its 4 output columns across the k-loop,
// so it accumulates sum-of-squares and applies 1/max(norm,1e-12) at epilogue.
// ---------------------------------------------------------------------------
__global__ __launch_bounds__(256) void gemm_norm_kernel(
    const float* __restrict__ proj,   // [M_TOT, D_DIM] row-major
    const float* __restrict__ Amat)   // [D_DIM, P_DIM] row-major
{
    __shared__ float As[BK][BM];   // transposed proj tile: As[k][m]
    __shared__ float Bs[BK][BN];   // Bs[k][n]

    const int tid = threadIdx.x;
    const int tx  = tid & 15;      // n-direction (4 cols each)
    const int ty  = tid >> 4;      // m-direction (8 rows each)
    const int bx  = blockIdx.x;    // n block
    const int by  = blockIdx.y;    // m block

    float acc[8][4];
    #pragma unroll
    for (int i = 0; i < 8; ++i)
        #pragma unroll
        for (int j = 0; j < 4; ++j) acc[i][j] = 0.f;
    float nsq[4] = {0.f, 0.f, 0.f, 0.f};

    const float4* projv = (const float4*)proj;
    const float4* Av    = (const float4*)Amat;

    for (int kt = 0; kt < D_DIM / BK; ++kt) {
        const int k0 = kt * BK;
        // Load proj tile (128 x 16), transpose into As[k][m]
        #pragma unroll
        for (int i = 0; i < 2; ++i) {
            int idx = tid + i * 256;       // 0..511 float4 slots
            int row = idx >> 2;            // 0..127
            int c4  = idx & 3;             // 0..3
            float4 v = projv[(size_t)(by * BM + row) * (D_DIM / 4) + kt * 4 + c4];
            As[c4 * 4 + 0][row] = v.x;
            As[c4 * 4 + 1][row] = v.y;
            As[c4 * 4 + 2][row] = v.z;
            As[c4 * 4 + 3][row] = v.w;
        }
        // Load A tile (16 x 64)
        {
            int r  = tid >> 4;             // 0..15 (k within tile)
            int c4 = tid & 15;             // 0..15 (float4 col)
            float4 v = Av[(size_t)(k0 + r) * (P_DIM / 4) + bx * (BN / 4) + c4];
            *(float4*)&Bs[r][c4 * 4] = v;
        }
        __syncthreads();

        #pragma unroll
        for (int k = 0; k < BK; ++k) {
            float4 a0 = *(const float4*)&As[k][ty * 8];
            float4 a1 = *(const float4*)&As[k][ty * 8 + 4];
            float4 b  = *(const float4*)&Bs[k][tx * 4];
            float af[8] = {a0.x, a0.y, a0.z, a0.w, a1.x, a1.y, a1.z, a1.w};
            float bf[4] = {b.x, b.y, b.z, b.w};
            nsq[0] += bf[0] * bf[0];
            nsq[1] += bf[1] * bf[1];
            nsq[2] += bf[2] * bf[2];
            nsq[3] += bf[3] * bf[3];
            #pragma unroll
            for (int i = 0; i < 8; ++i)
                #pragma unroll
                for (int j = 0; j < 4; ++j)
                    acc[i][j] += af[i] * bf[j];
        }
        __syncthreads();
    }

    float inv[4];
    #pragma unroll
    for (int j = 0; j < 4; ++j)
        inv[j] = 1.f / fmaxf(sqrtf(nsq[j]), 1e-12f);

    const int n0 = bx * BN + tx * 4;
    #pragma unroll
    for (int i = 0; i < 8; ++i) {
        int m = by * BM + ty * 8 + i;
        float4 o;
        o.x = acc[i][0] * inv[0];
        o.y = acc[i][1] * inv[1];
        o.z = acc[i][2] * inv[2];
        o.w = acc[i][3] * inv[3];
        *(float4*)&g_x[(size_t)m * P_DIM + n0] = o;
    }
}

// ---------------------------------------------------------------------------
// Kernel 2: per (t,p), accumulate cos/sin means over b via Chebyshev
// recurrence (ONE __sincosf per element instead of 17), then weighted error.
// Deterministic: block partials to g_partial, no float atomics.
// ---------------------------------------------------------------------------
__global__ __launch_bounds__(64) void trig_kernel()
{
    const int t = blockIdx.y;
    const int p = blockIdx.x * 64 + threadIdx.x;
    const float dt = 3.0f / 16.0f;   // 0.1875

    float ca[KNOTS - 1];   // k = 1..16 (k=0 term is identically zero)
    float sa[KNOTS - 1];
    #pragma unroll
    for (int k = 0; k < KNOTS - 1; ++k) { ca[k] = 0.f; sa[k] = 0.f; }

    const float* xp = g_x + (size_t)(t * B_DIM) * P_DIM + p;
    #pragma unroll 4
    for (int b = 0; b < B_DIM; ++b) {
        float x = xp[(size_t)b * P_DIM];
        float s1, c1;
        __sincosf(x * dt, &s1, &c1);
        float ckm = 1.f, skm = 0.f;
        float ck = c1, sk = s1;
        const float tc = 2.f * c1;
        #pragma unroll
        for (int k = 1; k <= 16; ++k) {
            ca[k - 1] += ck;
            sa[k - 1] += sk;
            float cn = tc * ck - ckm;
            float sn = tc * sk - skm;
            ckm = ck; skm = sk; ck = cn; sk = sn;
        }
    }

    float val = 0.f;
    const float invB = 1.f / (float)B_DIM;
    #pragma unroll
    for (int k = 1; k <= 16; ++k) {
        float tk   = (float)k * dt;
        float phik = expf(-0.5f * tk * tk);
        float wk   = ((k == 16) ? dt : 2.f * dt) * phik;
        float cm = ca[k - 1] * invB - phik;
        float sm = sa[k - 1] * invB;
        val += wk * (cm * cm + sm * sm);
    }
    val *= (float)B_DIM;   // * B

    __shared__ float red[64];
    red[threadIdx.x] = val;
    __syncthreads();
    #pragma unroll
    for (int s = 32; s > 0; s >>= 1) {
        if (threadIdx.x < s) red[threadIdx.x] += red[threadIdx.x + s];
        __syncthreads();
    }
    if (threadIdx.x == 0)
        g_partial[blockIdx.y * gridDim.x + blockIdx.x] = red[0];
}

// ---------------------------------------------------------------------------
// Kernel 3: final deterministic reduction of 512 partials, divide by T*P.
// ---------------------------------------------------------------------------
__global__ __launch_bounds__(512) void reduce_kernel(float* __restrict__ out)
{
    __shared__ float red[512];
    red[threadIdx.x] = g_partial[threadIdx.x];
    __syncthreads();
    #pragma unroll
    for (int s = 256; s > 0; s >>= 1) {
        if (threadIdx.x < s) red[threadIdx.x] += red[threadIdx.x + s];
        __syncthreads();
    }
    if (threadIdx.x == 0)
        out[0] = red[0] * (1.0f / (float)(T_DIM * P_DIM));
}

// ---------------------------------------------------------------------------
extern "C" void kernel_launch(void* const* d_in, const int* in_sizes, int n_in,
                              void* d_out, int out_size)
{
    const float* proj = (const float*)d_in[0];   // (32,64,256)
    const float* Amat = (const float*)d_in[1];   // (256,1024)
    float* out = (float*)d_out;

    dim3 g1(P_DIM / BN, M_TOT / BM);   // (16, 16)
    gemm_norm_kernel<<<g1, 256>>>(proj, Amat);

    dim3 g2(P_DIM / 64, T_DIM);        // (16, 32) -> 512 blocks
    trig_kernel<<<g2, 64>>>();

    reduce_kernel<<<1, 512>>>(out);
}